// round 14
// baseline (speedup 1.0000x reference)
#include <cuda_runtime.h>
#include <cstdint>
#include <cstddef>

// SparseConv2D via mma.sync (tf32, m16n8k8) implicit GEMM, rolling-row strips.
// out(h,c,co) = sum_{ky,kx,ci} x(h+ky, c+kx, ci) * w[ky][kx][ci][co],
// gated per 14x14 block by max(mask) > 0.5 (precomputed into g_scale).
//
// R14: 256-thread CTA, 8 warps; warps 0-3 compute output row h, warps 4-7 row
// h+1 (two rows per iteration). 4-slot input-row ring (slot = row % 4); the two
// next rows are prefetched into registers during compute. 2 CTAs/SM.

#define HIN   506
#define WIN   506
#define HOUT  504
#define WOUT  504
#define NB    36

#define NSTRIPS        32        // 8 batch * 4 column strips
#define CTAS_PER_STRIP 18
#define ROWS_PER_CTA   28        // 504 / 18 (even: 14 two-row iterations)
#define GRID_MAIN      (NSTRIPS * CTAS_PER_STRIP)   // 576
#define NTHREADS       256

// smem word layout (tf32 bits stored as u32):
//  ring:  4 slots of [130 px][stride 36] -> 4680 words each, 18720 total
//  BS:    swizzled B frags [9 tap][4 cc][4 s][32 lane] uint2 -> 9216 words
//  bias:  32 words
#define PATCH_STRIDE 36
#define KY_WORDS     (130 * PATCH_STRIDE)      // 4680
#define RING_SLOTS   4
#define PATCH_WORDS  (RING_SLOTS * KY_WORDS)   // 18720
#define BS_WOFF      PATCH_WORDS               // 18720
#define BIAS_WOFF    (BS_WOFF + 9216)          // 27936
#define SMEM_WORDS   (BIAS_WOFF + 32)          // 27968
#define SMEM_BYTES   (SMEM_WORDS * 4)          // 111872 (~109.25 KB)

__device__ float g_scale[8 * NB * NB];

__device__ __forceinline__ uint32_t f2tf(float f) {
    uint32_t r;
    asm("cvt.rna.tf32.f32 %0, %1;" : "=r"(r) : "f"(f));
    return r;
}

__device__ __forceinline__ void mma_tf32(float* c, uint32_t a0, uint32_t a1,
                                         uint32_t a2, uint32_t a3,
                                         uint32_t b0, uint32_t b1) {
    asm volatile("mma.sync.aligned.m16n8k8.row.col.f32.tf32.tf32.f32 "
                 "{%0,%1,%2,%3}, {%4,%5,%6,%7}, {%8,%9}, {%0,%1,%2,%3};"
                 : "+f"(c[0]), "+f"(c[1]), "+f"(c[2]), "+f"(c[3])
                 : "r"(a0), "r"(a1), "r"(a2), "r"(a3), "r"(b0), "r"(b1));
}

// ---------------- mask precompute: one CTA per (n,bh,bw) ----------------
__global__ void mask_kernel(const float* __restrict__ mask) {
    __shared__ float red[8];
    int b = blockIdx.x;
    int n = b / (NB * NB);
    int rem = b % (NB * NB);
    int bh = rem / NB, bw = rem % NB;
    int tid = threadIdx.x;              // 256 = 16x16
    int r = tid >> 4, c = tid & 15;
    float m = mask[((size_t)(n * HIN + bh * 14 + r)) * WIN + bw * 14 + c];
    #pragma unroll
    for (int off = 16; off; off >>= 1)
        m = fmaxf(m, __shfl_xor_sync(0xffffffffu, m, off));
    if ((tid & 31) == 0) red[tid >> 5] = m;
    __syncthreads();
    if (tid == 0) {
        float mm = red[0];
        #pragma unroll
        for (int i = 1; i < 8; i++) mm = fmaxf(mm, red[i]);
        g_scale[b] = (mm > 0.5f) ? 1.0f : 0.0f;
    }
}

// ---------------- main persistent kernel ----------------
__global__ __launch_bounds__(NTHREADS, 2)
void conv_mma_kernel(const float* __restrict__ x,
                     const float* __restrict__ wglob,
                     const float* __restrict__ bias,
                     float* __restrict__ out)
{
    extern __shared__ uint32_t sp[];
    const int tid  = threadIdx.x;
    const int wid  = tid >> 5;      // 0..7
    const int lane = tid & 31;
    const int g    = lane >> 2;     // fragment group row 0..7
    const int tq   = lane & 3;      // thread-in-group 0..3
    const int wrow = wid >> 2;      // 0: row h, 1: row h+1
    const int pbase = (wid & 3) * 32;   // warp covers px [pbase, pbase+32)

    // ---- strip / row-range assignment ----
    const int strip  = blockIdx.x / CTAS_PER_STRIP;       // 0..31
    const int rchunk = blockIdx.x % CTAS_PER_STRIP;       // 0..17
    const int n      = strip >> 2;                        // batch
    const int c0     = (strip & 3) << 7;                  // col base
    const int hstart = rchunk * ROWS_PER_CTA;
    const int hend   = hstart + ROWS_PER_CTA;

    // ---- build B once per CTA (stage raw weights in ring area, then swizzle) ----
    {
        const float4* w4 = reinterpret_cast<const float4*>(wglob);
        float4* st4 = reinterpret_cast<float4*>(sp);
        #pragma unroll 1
        for (int i = tid; i < 9216 / 4; i += NTHREADS)
            st4[i] = w4[i];
    }
    if (tid < 32) sp[BIAS_WOFF + tid] = __float_as_uint(bias[tid]);
    __syncthreads();
    {
        const float* stage = reinterpret_cast<const float*>(sp);
        #pragma unroll 1
        for (int idx = tid; idx < 4608; idx += NTHREADS) {
            int l   = idx & 31;
            int s   = (idx >> 5) & 3;
            int cc  = (idx >> 7) & 3;
            int tap = idx >> 9;
            int k   = cc * 8 + (l & 3);
            int nn  = s * 8 + (l >> 2);
            uint32_t b0 = f2tf(stage[tap * 1024 + k * 32 + nn]);
            uint32_t b1 = f2tf(stage[tap * 1024 + (k + 4) * 32 + nn]);
            sp[BS_WOFF + idx * 2]     = b0;
            sp[BS_WOFF + idx * 2 + 1] = b1;
        }
    }
    __syncthreads();

    // ---- initial build: input rows hstart .. hstart+3 into ring slots ----
    #pragma unroll 1
    for (int ky = 0; ky < 4; ky++) {
        int row = hstart + ky;
        #pragma unroll 1
        for (int id = tid; id < 1040; id += NTHREADS) {
            int c4 = id & 7;
            int j  = id >> 3;
            int col = c0 + j; if (col > 505) col = 505;
            const float4 v = *reinterpret_cast<const float4*>(
                x + (((size_t)(n * HIN + row)) * WIN + col) * 32 + c4 * 4);
            uint32_t* dst = sp + (row % RING_SLOTS) * KY_WORDS + j * PATCH_STRIDE + c4 * 4;
            dst[0] = f2tf(v.x);
            dst[1] = f2tf(v.y);
            dst[2] = f2tf(v.z);
            dst[3] = f2tf(v.w);
        }
    }
    __syncthreads();

    // ---- rolling sweep, two output rows per iteration ----
    #pragma unroll 1
    for (int h = hstart; h < hend; h += 2) {
        const int hw = h + wrow;            // this warp's output row

        // prefetch rows h+4, h+5 into registers during compute
        const bool havepf = (h + 2 < hend);
        float4 pf[9];                        // 2 * 1040 / 256 = 8.125 -> 9
        if (havepf) {
            #pragma unroll
            for (int k = 0; k < 9; k++) {
                int id = k * NTHREADS + tid;
                if (id < 2080) {
                    int rofs = (id >= 1040);
                    int e    = id - rofs * 1040;
                    int c4 = e & 7;
                    int j  = e >> 3;
                    int col = c0 + j; if (col > 505) col = 505;
                    pf[k] = *reinterpret_cast<const float4*>(
                        x + (((size_t)(n * HIN + h + 4 + rofs)) * WIN + col) * 32 + c4 * 4);
                }
            }
        }

        // compute: warp handles px [pbase, pbase+32) of row hw as two m16 tiles
        float acc[2][4][4];
        #pragma unroll
        for (int m = 0; m < 2; m++)
            #pragma unroll
            for (int s = 0; s < 4; s++)
                #pragma unroll
                for (int i = 0; i < 4; i++) acc[m][s][i] = 0.0f;

        #pragma unroll 1
        for (int ky = 0; ky < 3; ky++) {
            const uint32_t* kbuf = sp + ((hw + ky) % RING_SLOTS) * KY_WORDS;
            #pragma unroll
            for (int kx = 0; kx < 3; kx++) {
                const int tap = ky * 3 + kx;
                const uint32_t* arow0 = kbuf + (pbase + kx + g) * PATCH_STRIDE + tq;
                const uint32_t* arow1 = arow0 + 16 * PATCH_STRIDE;
                const uint32_t* brow = sp + BS_WOFF + tap * 1024 + lane * 2;
                #pragma unroll
                for (int cc = 0; cc < 4; cc++) {
                    uint32_t a0 = arow0[cc * 8];
                    uint32_t a1 = arow0[cc * 8 + 8 * PATCH_STRIDE];
                    uint32_t a2 = arow0[cc * 8 + 4];
                    uint32_t a3 = arow0[cc * 8 + 8 * PATCH_STRIDE + 4];
                    uint32_t a4 = arow1[cc * 8];
                    uint32_t a5 = arow1[cc * 8 + 8 * PATCH_STRIDE];
                    uint32_t a6 = arow1[cc * 8 + 4];
                    uint32_t a7 = arow1[cc * 8 + 8 * PATCH_STRIDE + 4];
                    #pragma unroll
                    for (int s = 0; s < 4; s++) {
                        const uint2 bb = *reinterpret_cast<const uint2*>(
                            brow + cc * 256 + s * 64);
                        mma_tf32(acc[0][s], a0, a1, a2, a3, bb.x, bb.y);
                        mma_tf32(acc[1][s], a4, a5, a6, a7, bb.x, bb.y);
                    }
                }
            }
        }

        // epilogue: per m-tile, thread owns px {pbase+m*16+g, +8}, couts s*8+2*tq+{0,1}
        {
            const float* bias_s = reinterpret_cast<const float*>(sp + BIAS_WOFF);
            const int srow = (n * NB + hw / 14) * NB;
            #pragma unroll
            for (int m = 0; m < 2; m++) {
                const int colA = c0 + pbase + m * 16 + g;
                const int colB = colA + 8;
                float scA = 0.0f, scB = 0.0f;
                if (colA < WOUT) scA = g_scale[srow + colA / 14];
                if (colB < WOUT) scB = g_scale[srow + colB / 14];
                float* opA = out + ((size_t)(n * HOUT + hw) * WOUT + colA) * 32;
                float* opB = out + ((size_t)(n * HOUT + hw) * WOUT + colB) * 32;
                #pragma unroll
                for (int s = 0; s < 4; s++) {
                    const int co = s * 8 + 2 * tq;
                    const float b0 = bias_s[co], b1 = bias_s[co + 1];
                    if (colA < WOUT) {
                        float2 v = make_float2((acc[m][s][0] + b0) * scA,
                                               (acc[m][s][1] + b1) * scA);
                        *reinterpret_cast<float2*>(opA + co) = v;
                    }
                    if (colB < WOUT) {
                        float2 v = make_float2((acc[m][s][2] + b0) * scB,
                                               (acc[m][s][3] + b1) * scB);
                        *reinterpret_cast<float2*>(opB + co) = v;
                    }
                }
            }
        }

        __syncthreads();     // all reads of slots h%4 and (h+1)%4 complete

        if (havepf) {
            #pragma unroll
            for (int k = 0; k < 9; k++) {
                int id = k * NTHREADS + tid;
                if (id < 2080) {
                    int rofs = (id >= 1040);
                    int e    = id - rofs * 1040;
                    int c4 = e & 7;
                    int j  = e >> 3;
                    // row h+4 -> slot h%4, row h+5 -> slot (h+1)%4
                    int slot = (h + rofs) % RING_SLOTS;
                    uint32_t* dst = sp + slot * KY_WORDS + j * PATCH_STRIDE + c4 * 4;
                    dst[0] = f2tf(pf[k].x);
                    dst[1] = f2tf(pf[k].y);
                    dst[2] = f2tf(pf[k].z);
                    dst[3] = f2tf(pf[k].w);
                }
            }
        }
        __syncthreads();     // new rows visible before next compute
    }
}

extern "C" void kernel_launch(void* const* d_in, const int* in_sizes, int n_in,
                              void* d_out, int out_size)
{
    const float* x    = (const float*)d_in[0];
    const float* mask = (const float*)d_in[1];
    const float* w    = (const float*)d_in[2];
    const float* bias = (const float*)d_in[3];
    float* out        = (float*)d_out;
    (void)in_sizes; (void)n_in; (void)out_size;

    cudaFuncSetAttribute(conv_mma_kernel,
                         cudaFuncAttributeMaxDynamicSharedMemorySize, SMEM_BYTES);

    mask_kernel<<<8 * NB * NB, 256>>>(mask);
    conv_mma_kernel<<<GRID_MAIN, NTHREADS, SMEM_BYTES>>>(x, w, bias, out);
}

// round 15
// speedup vs baseline: 1.5204x; 1.5204x over previous
#include <cuda_runtime.h>
#include <cstdint>
#include <cstddef>

// SparseConv2D via mma.sync (tf32, m16n8k8) implicit GEMM, rolling-row strips.
// out(h,c,co) = sum_{ky,kx,ci} x(h+ky, c+kx, ci) * w[ky][kx][ci][co],
// gated per 14x14 block by max(mask) > 0.5 (precomputed into g_scale).
//
// R15 = R13 geometry (128 thr / 4 warps, 2 CTA/SM, warp M=32) + explicit
// double-buffered fragment pipeline over the 36 linearized k-steps.

#define HIN   506
#define WIN   506
#define HOUT  504
#define WOUT  504
#define NB    36

#define NSTRIPS        32        // 8 batch * 4 column strips
#define CTAS_PER_STRIP 18
#define ROWS_PER_CTA   28        // 504 / 18
#define GRID_MAIN      (NSTRIPS * CTAS_PER_STRIP)   // 576
#define NTHREADS       128

// smem word layout (tf32 bits stored as u32):
//  ring:  3 slots of [130 px][stride 36] -> 4680 words each, 14040 total
//  BS:    swizzled B frags [9 tap][4 cc][4 s][32 lane] uint2 -> 9216 words
//  bias:  32 words
#define PATCH_STRIDE 36
#define KY_WORDS     (130 * PATCH_STRIDE)      // 4680
#define PATCH_WORDS  (3 * KY_WORDS)            // 14040
#define BS_WOFF      PATCH_WORDS               // 14040
#define BIAS_WOFF    (BS_WOFF + 9216)          // 23256
#define SMEM_WORDS   (BIAS_WOFF + 32)          // 23288
#define SMEM_BYTES   (SMEM_WORDS * 4)          // 93152

__device__ float g_scale[8 * NB * NB];

__device__ __forceinline__ uint32_t f2tf(float f) {
    uint32_t r;
    asm("cvt.rna.tf32.f32 %0, %1;" : "=r"(r) : "f"(f));
    return r;
}

__device__ __forceinline__ void mma_tf32(float* c, uint32_t a0, uint32_t a1,
                                         uint32_t a2, uint32_t a3,
                                         uint32_t b0, uint32_t b1) {
    asm volatile("mma.sync.aligned.m16n8k8.row.col.f32.tf32.tf32.f32 "
                 "{%0,%1,%2,%3}, {%4,%5,%6,%7}, {%8,%9}, {%0,%1,%2,%3};"
                 : "+f"(c[0]), "+f"(c[1]), "+f"(c[2]), "+f"(c[3])
                 : "r"(a0), "r"(a1), "r"(a2), "r"(a3), "r"(b0), "r"(b1));
}

// ---------------- mask precompute: one CTA per (n,bh,bw) ----------------
__global__ void mask_kernel(const float* __restrict__ mask) {
    __shared__ float red[8];
    int b = blockIdx.x;
    int n = b / (NB * NB);
    int rem = b % (NB * NB);
    int bh = rem / NB, bw = rem % NB;
    int tid = threadIdx.x;              // 256 = 16x16
    int r = tid >> 4, c = tid & 15;
    float m = mask[((size_t)(n * HIN + bh * 14 + r)) * WIN + bw * 14 + c];
    #pragma unroll
    for (int off = 16; off; off >>= 1)
        m = fmaxf(m, __shfl_xor_sync(0xffffffffu, m, off));
    if ((tid & 31) == 0) red[tid >> 5] = m;
    __syncthreads();
    if (tid == 0) {
        float mm = red[0];
        #pragma unroll
        for (int i = 1; i < 8; i++) mm = fmaxf(mm, red[i]);
        g_scale[b] = (mm > 0.5f) ? 1.0f : 0.0f;
    }
}

// ---------------- main persistent kernel ----------------
__global__ __launch_bounds__(NTHREADS, 2)
void conv_mma_kernel(const float* __restrict__ x,
                     const float* __restrict__ wglob,
                     const float* __restrict__ bias,
                     float* __restrict__ out)
{
    extern __shared__ uint32_t sp[];
    const int tid  = threadIdx.x;
    const int wid  = tid >> 5;      // 0..3
    const int lane = tid & 31;
    const int g    = lane >> 2;     // fragment group row 0..7
    const int tq   = lane & 3;      // thread-in-group 0..3

    // ---- strip / row-range assignment ----
    const int strip  = blockIdx.x / CTAS_PER_STRIP;       // 0..31
    const int rchunk = blockIdx.x % CTAS_PER_STRIP;       // 0..17
    const int n      = strip >> 2;                        // batch
    const int c0     = (strip & 3) << 7;                  // col base
    const int hstart = rchunk * ROWS_PER_CTA;
    const int hend   = hstart + ROWS_PER_CTA;

    // ---- build B once per CTA (stage raw weights in ring area, then swizzle) ----
    {
        const float4* w4 = reinterpret_cast<const float4*>(wglob);
        float4* st4 = reinterpret_cast<float4*>(sp);
        #pragma unroll 1
        for (int i = tid; i < 9216 / 4; i += NTHREADS)
            st4[i] = w4[i];
    }
    if (tid < 32) sp[BIAS_WOFF + tid] = __float_as_uint(bias[tid]);
    __syncthreads();
    {
        const float* stage = reinterpret_cast<const float*>(sp);
        #pragma unroll 1
        for (int idx = tid; idx < 4608; idx += NTHREADS) {
            int l   = idx & 31;
            int s   = (idx >> 5) & 3;
            int cc  = (idx >> 7) & 3;
            int tap = idx >> 9;
            int k   = cc * 8 + (l & 3);
            int nn  = s * 8 + (l >> 2);
            uint32_t b0 = f2tf(stage[tap * 1024 + k * 32 + nn]);
            uint32_t b1 = f2tf(stage[tap * 1024 + (k + 4) * 32 + nn]);
            sp[BS_WOFF + idx * 2]     = b0;
            sp[BS_WOFF + idx * 2 + 1] = b1;
        }
    }
    __syncthreads();

    // ---- initial build: input rows hstart .. hstart+2 into ring slots ----
    #pragma unroll 1
    for (int id = tid; id < 3120; id += NTHREADS) {
        int c4 = id & 7;
        int jj = id >> 3;
        int j  = jj % 130;
        int ky = jj / 130;
        int row = hstart + ky;
        int col = c0 + j; if (col > 505) col = 505;
        const float4 v = *reinterpret_cast<const float4*>(
            x + (((size_t)(n * HIN + row)) * WIN + col) * 32 + c4 * 4);
        uint32_t* dst = sp + (row % 3) * KY_WORDS + j * PATCH_STRIDE + c4 * 4;
        dst[0] = f2tf(v.x);
        dst[1] = f2tf(v.y);
        dst[2] = f2tf(v.z);
        dst[3] = f2tf(v.w);
    }
    __syncthreads();

    const int pbase = wid * 32;     // warp covers px [pbase, pbase+32)
    const uint32_t* brbase = sp + BS_WOFF + lane * 2;

    // ---- rolling sweep over output rows ----
    #pragma unroll 1
    for (int h = hstart; h < hend; ++h) {
        // prefetch next input row (h+3) into registers during compute
        const bool havepf = (h + 1 < hend);
        float4 pf[9];
        if (havepf) {
            const int prow = h + 3;
            #pragma unroll
            for (int k = 0; k < 9; k++) {
                int id = tid + k * NTHREADS;
                if (id < 1040) {
                    int c4 = id & 7;
                    int j  = id >> 3;
                    int col = c0 + j; if (col > 505) col = 505;
                    pf[k] = *reinterpret_cast<const float4*>(
                        x + (((size_t)(n * HIN + prow)) * WIN + col) * 32 + c4 * 4);
                }
            }
        }

        // per-tap A base word-indices into sp (ky ring slot + px offset)
        uint32_t aoff[9];
        #pragma unroll
        for (int tap = 0; tap < 9; tap++) {
            int ky = tap / 3, kx = tap % 3;
            aoff[tap] = ((h + ky) % 3) * KY_WORDS +
                        (pbase + kx + g) * PATCH_STRIDE + tq;
        }

        // compute: double-buffered fragment pipeline over 36 k-steps
        float acc[2][4][4];
        #pragma unroll
        for (int m = 0; m < 2; m++)
            #pragma unroll
            for (int s = 0; s < 4; s++)
                #pragma unroll
                for (int i = 0; i < 4; i++) acc[m][s][i] = 0.0f;

        uint32_t af[2][8];
        uint2    bf[2][4];

        // preload k-step 0 (tap 0, cc 0)
        {
            const uint32_t* ar = sp + aoff[0];
            af[0][0] = ar[0];
            af[0][1] = ar[8 * PATCH_STRIDE];
            af[0][2] = ar[4];
            af[0][3] = ar[8 * PATCH_STRIDE + 4];
            af[0][4] = ar[16 * PATCH_STRIDE];
            af[0][5] = ar[24 * PATCH_STRIDE];
            af[0][6] = ar[16 * PATCH_STRIDE + 4];
            af[0][7] = ar[24 * PATCH_STRIDE + 4];
            #pragma unroll
            for (int s = 0; s < 4; s++)
                bf[0][s] = *reinterpret_cast<const uint2*>(brbase + s * 64);
        }

        #pragma unroll
        for (int kk = 0; kk < 36; kk++) {
            const int p = kk & 1;
            if (kk < 35) {
                const int nk  = kk + 1;
                const int ntap = nk >> 2;
                const int ncc  = nk & 3;
                const uint32_t* ar = sp + aoff[ntap] + ncc * 8;
                af[p ^ 1][0] = ar[0];
                af[p ^ 1][1] = ar[8 * PATCH_STRIDE];
                af[p ^ 1][2] = ar[4];
                af[p ^ 1][3] = ar[8 * PATCH_STRIDE + 4];
                af[p ^ 1][4] = ar[16 * PATCH_STRIDE];
                af[p ^ 1][5] = ar[24 * PATCH_STRIDE];
                af[p ^ 1][6] = ar[16 * PATCH_STRIDE + 4];
                af[p ^ 1][7] = ar[24 * PATCH_STRIDE + 4];
                const uint32_t* br = brbase + ntap * 1024 + ncc * 256;
                #pragma unroll
                for (int s = 0; s < 4; s++)
                    bf[p ^ 1][s] = *reinterpret_cast<const uint2*>(br + s * 64);
            }
            #pragma unroll
            for (int s = 0; s < 4; s++) {
                mma_tf32(acc[0][s], af[p][0], af[p][1], af[p][2], af[p][3],
                         bf[p][s].x, bf[p][s].y);
                mma_tf32(acc[1][s], af[p][4], af[p][5], af[p][6], af[p][7],
                         bf[p][s].x, bf[p][s].y);
            }
        }

        // epilogue: per m-tile, thread owns px {pbase+m*16+g, +8}, couts s*8+2*tq+{0,1}
        {
            const float* bias_s = reinterpret_cast<const float*>(sp + BIAS_WOFF);
            const int srow = (n * NB + h / 14) * NB;
            #pragma unroll
            for (int m = 0; m < 2; m++) {
                const int colA = c0 + pbase + m * 16 + g;
                const int colB = colA + 8;
                float scA = 0.0f, scB = 0.0f;
                if (colA < WOUT) scA = g_scale[srow + colA / 14];
                if (colB < WOUT) scB = g_scale[srow + colB / 14];
                float* opA = out + ((size_t)(n * HOUT + h) * WOUT + colA) * 32;
                float* opB = out + ((size_t)(n * HOUT + h) * WOUT + colB) * 32;
                #pragma unroll
                for (int s = 0; s < 4; s++) {
                    const int co = s * 8 + 2 * tq;
                    const float b0 = bias_s[co], b1 = bias_s[co + 1];
                    if (colA < WOUT) {
                        float2 v = make_float2((acc[m][s][0] + b0) * scA,
                                               (acc[m][s][1] + b1) * scA);
                        *reinterpret_cast<float2*>(opA + co) = v;
                    }
                    if (colB < WOUT) {
                        float2 v = make_float2((acc[m][s][2] + b0) * scB,
                                               (acc[m][s][3] + b1) * scB);
                        *reinterpret_cast<float2*>(opB + co) = v;
                    }
                }
            }
        }

        __syncthreads();     // everyone done reading ring slot h%3

        if (havepf) {
            const int slot = h % 3;          // == (h+3) % 3
            #pragma unroll
            for (int k = 0; k < 9; k++) {
                int id = tid + k * NTHREADS;
                if (id < 1040) {
                    int c4 = id & 7;
                    int j  = id >> 3;
                    uint32_t* dst = sp + slot * KY_WORDS + j * PATCH_STRIDE + c4 * 4;
                    dst[0] = f2tf(pf[k].x);
                    dst[1] = f2tf(pf[k].y);
                    dst[2] = f2tf(pf[k].z);
                    dst[3] = f2tf(pf[k].w);
                }
            }
        }
        __syncthreads();     // new row visible before next compute
    }
}

extern "C" void kernel_launch(void* const* d_in, const int* in_sizes, int n_in,
                              void* d_out, int out_size)
{
    const float* x    = (const float*)d_in[0];
    const float* mask = (const float*)d_in[1];
    const float* w    = (const float*)d_in[2];
    const float* bias = (const float*)d_in[3];
    float* out        = (float*)d_out;
    (void)in_sizes; (void)n_in; (void)out_size;

    cudaFuncSetAttribute(conv_mma_kernel,
                         cudaFuncAttributeMaxDynamicSharedMemorySize, SMEM_BYTES);

    mask_kernel<<<8 * NB * NB, 256>>>(mask);
    conv_mma_kernel<<<GRID_MAIN, NTHREADS, SMEM_BYTES>>>(x, w, bias, out);
}